// round 11
// baseline (speedup 1.0000x reference)
#include <cuda_runtime.h>
#include <math.h>
#include <stdint.h>

#define BB   2
#define NN   2048
#define DIM  512
#define NH   8
#define KNBR 32
#define PD   16
#define HD   64
#define FF   2048

// ======================= helpers =============================================
__device__ __forceinline__ uint32_t smem_u32(const void* p) {
    uint32_t a;
    asm("{ .reg .u64 t; cvta.to.shared.u64 t, %1; cvt.u32.u64 %0, t; }"
        : "=r"(a) : "l"(p));
    return a;
}

__device__ __forceinline__ float rtf32(float x) {
    uint32_t u;
    asm("cvt.rna.tf32.f32 %0, %1;" : "=r"(u) : "f"(x));
    return __uint_as_float(u);
}

// ======================= scratch =============================================
__device__ float g_xnorm[BB*NN*DIM];
__device__ float g_qkv[3*BB*NN*DIM];          // q | k | v (heads layout each)
__device__ float g_dist[(size_t)BB*NN*NN];
__device__ int   g_tidx[BB*NN*KNBR];
__device__ float g_tdist[BB*NN*KNBR];
__device__ float g_attn[BB*NN*DIM];
__device__ float g_x1[BB*NN*DIM];
__device__ float g_x2n[BB*NN*DIM];
__device__ float g_h1[(size_t)BB*NN*FF];
__device__ float g_pnsq[BB*NN];
// transposed (N,K) tf32-rounded weights
__device__ float g_wqkvt[3*DIM*DIM];          // fused QKV [1536, 512]
__device__ float g_bqkv[3*DIM];
__device__ float g_wot[DIM*DIM];
__device__ float g_w1t[FF*DIM];
__device__ float g_w2t[DIM*FF];

// ======================= batched weight transpose (+tf32 round) ==============
struct TJobs {
    const float* in[6];
    float* out[6];
    int R[6], C[6];
};

__global__ __launch_bounds__(256) void transpose_batch(TJobs jobs)
{
    int z = blockIdx.z;
    int R = jobs.R[z], C = jobs.C[z];
    int c0 = blockIdx.x * 32, r0 = blockIdx.y * 32;
    if (c0 >= C || r0 >= R) return;
    const float* in = jobs.in[z];
    float* out = jobs.out[z];
    __shared__ float t[32][33];
    int x = threadIdx.x, y = threadIdx.y;
#pragma unroll
    for (int dy = 0; dy < 32; dy += 8)
        t[y + dy][x] = in[(size_t)(r0 + y + dy) * C + c0 + x];
    __syncthreads();
#pragma unroll
    for (int dy = 0; dy < 32; dy += 8)
        out[(size_t)(c0 + y + dy) * R + r0 + x] = rtf32(t[x][y + dy]);
}

__global__ void concat_bias(const float* __restrict__ bq,
                            const float* __restrict__ bk,
                            const float* __restrict__ bv)
{
    int i = blockIdx.x * blockDim.x + threadIdx.x;
    if (i < 3 * DIM) {
        float v = (i < DIM) ? bq[i] : (i < 2 * DIM ? bk[i - DIM] : bv[i - 2 * DIM]);
        g_bqkv[i] = v;
    }
}

// ======================= mma.sync tf32 GEMM ==================================
// C[M,Nd] = A[M,Kd] @ Bt[Nd,Kd]^T + epilogue
// EPI: 1 = fused-QKV heads layout (+bias), 2 = +bias+resid, 3 = gelu(acc+bias)
// Tiles: CTA 128x128, BK=32, 2-stage cp.async, 8 warps of 32x64, 2 CTAs/SM.

#define SA 36                        // padded row stride (floats)
#define STAGE_FLOATS (2 * 128 * SA)  // A tile + B tile = 9216 floats
#define SMEM_FLOATS  (2 * STAGE_FLOATS)
#define GEMM_SMEM_BYTES (SMEM_FLOATS * 4)   // 73728

__device__ __forceinline__ void issue_tile(
    const float* __restrict__ A, const float* __restrict__ Bt,
    float* sm, int row0, int col0, int Kd, int t, int tid)
{
    float* as = sm + (t & 1) * STAGE_FLOATS;
    float* bs = as + 128 * SA;
    int k0 = t * 32;
#pragma unroll
    for (int it = 0; it < 4; it++) {
        int cch = tid + it * 256;            // 0..1023
        int r = cch >> 3, k4 = (cch & 7) * 4;
        uint32_t da = smem_u32(as + r * SA + k4);
        const float* ga = A + (size_t)(row0 + r) * Kd + k0 + k4;
        asm volatile("cp.async.cg.shared.global [%0], [%1], 16;" :: "r"(da), "l"(ga));
        uint32_t db = smem_u32(bs + r * SA + k4);
        const float* gb = Bt + (size_t)(col0 + r) * Kd + k0 + k4;
        asm volatile("cp.async.cg.shared.global [%0], [%1], 16;" :: "r"(db), "l"(gb));
    }
    asm volatile("cp.async.commit_group;" ::: "memory");
}

template<int EPI>
__global__ __launch_bounds__(256, 2) void mma_gemm(
    const float* __restrict__ A, const float* __restrict__ Bt,
    const float* __restrict__ bias, const float* __restrict__ resid,
    float* __restrict__ C, int M, int Nd, int Kd)
{
    extern __shared__ __align__(16) float sm[];
    int tid = threadIdx.x, wid = tid >> 5, lane = tid & 31;
    int g = lane >> 2, tig = lane & 3;
    int row0 = blockIdx.y * 128, col0 = blockIdx.x * 128;
    int m0 = (wid & 3) * 32, n0 = (wid >> 2) * 64;

    float acc[2][8][4];
#pragma unroll
    for (int mt = 0; mt < 2; mt++)
#pragma unroll
        for (int nt = 0; nt < 8; nt++)
#pragma unroll
            for (int u = 0; u < 4; u++) acc[mt][nt][u] = 0.f;

    const int tiles = Kd >> 5;
    issue_tile(A, Bt, sm, row0, col0, Kd, 0, tid);

    for (int t = 0; t < tiles; t++) {
        if (t + 1 < tiles) {
            issue_tile(A, Bt, sm, row0, col0, Kd, t + 1, tid);
            asm volatile("cp.async.wait_group 1;" ::: "memory");
        } else {
            asm volatile("cp.async.wait_group 0;" ::: "memory");
        }
        __syncthreads();

        const float* as = sm + (t & 1) * STAGE_FLOATS;
        const float* bs = as + 128 * SA;
#pragma unroll
        for (int kk = 0; kk < 32; kk += 8) {
            uint32_t a[2][4];
#pragma unroll
            for (int mt = 0; mt < 2; mt++) {
                const float* ar0 = as + (m0 + mt * 16 + g) * SA + kk;
                const float* ar1 = as + (m0 + mt * 16 + g + 8) * SA + kk;
                a[mt][0] = __float_as_uint(ar0[tig]);
                a[mt][1] = __float_as_uint(ar1[tig]);
                a[mt][2] = __float_as_uint(ar0[tig + 4]);
                a[mt][3] = __float_as_uint(ar1[tig + 4]);
            }
            uint32_t b[8][2];
#pragma unroll
            for (int nt = 0; nt < 8; nt++) {
                const float* br = bs + (n0 + nt * 8 + g) * SA + kk;
                b[nt][0] = __float_as_uint(br[tig]);
                b[nt][1] = __float_as_uint(br[tig + 4]);
            }
#pragma unroll
            for (int mt = 0; mt < 2; mt++)
#pragma unroll
                for (int nt = 0; nt < 8; nt++)
                    asm volatile(
                        "mma.sync.aligned.m16n8k8.row.col.f32.tf32.tf32.f32 "
                        "{%0,%1,%2,%3}, {%4,%5,%6,%7}, {%8,%9}, {%0,%1,%2,%3};"
                        : "+f"(acc[mt][nt][0]), "+f"(acc[mt][nt][1]),
                          "+f"(acc[mt][nt][2]), "+f"(acc[mt][nt][3])
                        : "r"(a[mt][0]), "r"(a[mt][1]), "r"(a[mt][2]), "r"(a[mt][3]),
                          "r"(b[nt][0]), "r"(b[nt][1]));
        }
        __syncthreads();
    }

    // ---- epilogue straight from registers ----
#pragma unroll
    for (int mt = 0; mt < 2; mt++) {
        int ra = row0 + m0 + mt * 16 + g;      // rows ra and ra+8
#pragma unroll
        for (int nt = 0; nt < 8; nt++) {
            int cc = col0 + n0 + nt * 8 + tig * 2;
            float b0 = bias[cc], b1 = bias[cc + 1];
            float v0 = acc[mt][nt][0] + b0, v1 = acc[mt][nt][1] + b1;
            float v2 = acc[mt][nt][2] + b0, v3 = acc[mt][nt][3] + b1;

            if (EPI == 1) {
                // fused QKV: cc in [0,1536): which = q/k/v, then heads layout
                int which = cc >> 9;
                int rem = cc & 511;
                int h = rem >> 6, d0 = rem & 63;
                float* base = C + (size_t)which * (BB * NN * DIM);
                int bb0 = ra >> 11, n_0 = ra & (NN - 1);
                int bb1 = (ra + 8) >> 11, n_1 = (ra + 8) & (NN - 1);
                float* d0p = base + (((size_t)bb0 * NH + h) * NN + n_0) * HD + d0;
                float* d1p = base + (((size_t)bb1 * NH + h) * NN + n_1) * HD + d0;
                *(float2*)d0p = make_float2(v0, v1);
                *(float2*)d1p = make_float2(v2, v3);
            } else if (EPI == 2) {
                float* p0 = C + (size_t)ra * Nd + cc;
                float* p1 = C + (size_t)(ra + 8) * Nd + cc;
                float2 rv0 = *(const float2*)(resid + (size_t)ra * Nd + cc);
                float2 rv1 = *(const float2*)(resid + (size_t)(ra + 8) * Nd + cc);
                *(float2*)p0 = make_float2(v0 + rv0.x, v1 + rv0.y);
                *(float2*)p1 = make_float2(v2 + rv1.x, v3 + rv1.y);
            } else { // gelu -> tf32
                float vv[4] = {v0, v1, v2, v3};
#pragma unroll
                for (int u = 0; u < 4; u++) {
                    float xg = vv[u];
                    float tt = 0.7978845608028654f * (xg + 0.044715f * xg * xg * xg);
                    vv[u] = rtf32(0.5f * xg * (1.f + tanhf(tt)));
                }
                float* p0 = C + (size_t)ra * Nd + cc;
                float* p1 = C + (size_t)(ra + 8) * Nd + cc;
                *(float2*)p0 = make_float2(vv[0], vv[1]);
                *(float2*)p1 = make_float2(vv[2], vv[3]);
            }
        }
    }
}

// ======================= LayerNorm (tf32-rounded output) =====================
__global__ __launch_bounds__(256) void ln_kernel(
    const float* __restrict__ x, const float* __restrict__ scale,
    const float* __restrict__ bias, float* __restrict__ out)
{
    int row = blockIdx.x;
    int tid = threadIdx.x;
    const float* xr = x + (size_t)row * DIM;
    float2 v = ((const float2*)xr)[tid];
    float s  = v.x + v.y;
    float ss = v.x*v.x + v.y*v.y;
    for (int o = 16; o; o >>= 1) {
        s  += __shfl_xor_sync(0xffffffffu, s,  o);
        ss += __shfl_xor_sync(0xffffffffu, ss, o);
    }
    __shared__ float sh_s[8], sh_ss[8];
    int warp = tid >> 5, lane = tid & 31;
    if (lane == 0) { sh_s[warp] = s; sh_ss[warp] = ss; }
    __syncthreads();
    float stot = 0.f, sstot = 0.f;
#pragma unroll
    for (int w = 0; w < 8; w++) { stot += sh_s[w]; sstot += sh_ss[w]; }
    float mean = stot * (1.0f / DIM);
    float var  = sstot * (1.0f / DIM) - mean * mean;
    float inv  = rsqrtf(var + 1e-6f);
    float2 sc = ((const float2*)scale)[tid];
    float2 bi = ((const float2*)bias)[tid];
    float2 o2;
    o2.x = rtf32((v.x - mean) * inv * sc.x + bi.x);
    o2.y = rtf32((v.y - mean) * inv * sc.y + bi.y);
    ((float2*)(out + (size_t)row * DIM))[tid] = o2;
}

// ======================= position squared norms ==============================
__global__ void pnsq_kernel(const float* __restrict__ pos)
{
    int r = blockIdx.x * blockDim.x + threadIdx.x;
    if (r < BB * NN) {
        float s = 0.f;
#pragma unroll
        for (int p = 0; p < PD; p++) { float v = pos[(size_t)r * PD + p]; s += v * v; }
        g_pnsq[r] = s;
    }
}

// ======================= Poincare distance matrix ============================
__global__ __launch_bounds__(256) void dist_kernel(
    const float* __restrict__ pos, const float* __restrict__ cptr)
{
    int b  = blockIdx.z;
    int i0 = blockIdx.y * 32, j0 = blockIdx.x * 32;
    __shared__ float pi[32][17], pj[32][17];
    __shared__ float ni[32], nj[32];
    int tid = threadIdx.x + threadIdx.y * 32;
    for (int t = tid; t < 512; t += 256) {
        int r = t >> 4, p = t & 15;
        pi[r][p] = pos[((size_t)b * NN + i0 + r) * PD + p];
        pj[r][p] = pos[((size_t)b * NN + j0 + r) * PD + p];
    }
    if (tid < 32) { ni[tid] = g_pnsq[b * NN + i0 + tid]; nj[tid] = g_pnsq[b * NN + j0 + tid]; }
    __syncthreads();
    float c = cptr[0];
    float rsc = rsqrtf(c);
    int j = threadIdx.x;
    float onj = 1.f - c * nj[j];
    for (int iy = threadIdx.y; iy < 32; iy += 8) {
        float ds = 0.f;
#pragma unroll
        for (int p = 0; p < PD; p++) { float d = pi[iy][p] - pj[j][p]; ds += d * d; }
        float den = (1.f - c * ni[iy]) * onj;
        den = fmaxf(den, 1e-8f);
        float arg = 1.f + 2.f * c * ds / den;
        arg = fmaxf(arg, 1.f + 1e-7f);
        g_dist[((size_t)b * NN + (i0 + iy)) * NN + (j0 + j)] = acoshf(arg) * rsc;
    }
}

// ======================= top-K per row =======================================
__global__ __launch_bounds__(256) void topk_kernel()
{
    const float INF = __int_as_float(0x7f800000);
    int row = blockIdx.x;
    int tid = threadIdx.x;
    __shared__ float sd[NN];
    __shared__ float rv[256];
    __shared__ int   ri[256];
    const float* dr = g_dist + (size_t)row * NN;
    for (int t = tid; t < NN; t += 256) sd[t] = dr[t];
    __syncthreads();
    for (int it = 0; it < KNBR; it++) {
        float best = INF; int bi = NN;
        for (int t = tid; t < NN; t += 256) {
            float v = sd[t];
            if (v < best) { best = v; bi = t; }
        }
        rv[tid] = best; ri[tid] = bi;
        __syncthreads();
        for (int s = 128; s > 0; s >>= 1) {
            if (tid < s) {
                float v2 = rv[tid + s]; int i2 = ri[tid + s];
                if (v2 < rv[tid] || (v2 == rv[tid] && i2 < ri[tid])) { rv[tid] = v2; ri[tid] = i2; }
            }
            __syncthreads();
        }
        if (tid == 0) {
            g_tidx [(size_t)row * KNBR + it] = ri[0];
            g_tdist[(size_t)row * KNBR + it] = rv[0];
            sd[ri[0]] = INF;
        }
        __syncthreads();
    }
}

// ======================= kNN attention (warp per (b,h,i)) ====================
__global__ __launch_bounds__(256) void attn_kernel(
    const float* __restrict__ log_tau, const float* __restrict__ attn_scale)
{
    const float* gq = g_qkv;
    const float* gk = g_qkv + BB * NN * DIM;
    const float* gv = g_qkv + 2 * BB * NN * DIM;

    int warp = threadIdx.x >> 5, lane = threadIdx.x & 31;
    int gw = blockIdx.x * 8 + warp;
    int i  = gw % NN;
    int bh = gw / NN;
    int b  = bh / NH, h = bh % NH;

    __shared__ float qs[8][64];
    __shared__ float ws[8][32];
    __shared__ int   is[8][32];

    const float* qrow = gq + ((size_t)bh * NN + i) * HD;
    qs[warp][lane]      = qrow[lane];
    qs[warp][lane + 32] = qrow[lane + 32];
    __syncwarp();

    int rowk  = b * NN + i;
    int idx   = g_tidx [(size_t)rowk * KNBR + lane];
    float dj  = g_tdist[(size_t)rowk * KNBR + lane];

    const float* krow = gk + ((size_t)bh * NN + idx) * HD;
    float dot = 0.f;
#pragma unroll
    for (int d4 = 0; d4 < HD; d4 += 4) {
        float4 kv = *(const float4*)(krow + d4);
        dot += qs[warp][d4] * kv.x + qs[warp][d4 + 1] * kv.y
             + qs[warp][d4 + 2] * kv.z + qs[warp][d4 + 3] * kv.w;
    }
    float tau = fmaxf(expf(log_tau[0]), 1e-8f);
    float s = attn_scale[0] * tanhf(dot * 0.125f - dj / tau);

    float m = s;
    for (int o = 16; o; o >>= 1) m = fmaxf(m, __shfl_xor_sync(0xffffffffu, m, o));
    float e = expf(s - m);
    float sum = e;
    for (int o = 16; o; o >>= 1) sum += __shfl_xor_sync(0xffffffffu, sum, o);
    float w = e / sum;

    ws[warp][lane] = w; is[warp][lane] = idx;
    __syncwarp();

    float a0 = 0.f, a1 = 0.f;
#pragma unroll
    for (int j = 0; j < KNBR; j++) {
        const float* vrow = gv + ((size_t)bh * NN + is[warp][j]) * HD;
        float wj = ws[warp][j];
        a0 += wj * vrow[lane];
        a1 += wj * vrow[lane + 32];
    }
    float* orow = g_attn + ((size_t)(b * NN + i)) * DIM + h * HD;
    orow[lane]      = rtf32(a0);
    orow[lane + 32] = rtf32(a1);
}

// ======================= launch ==============================================
extern "C" void kernel_launch(void* const* d_in, const int* in_sizes, int n_in,
                              void* d_out, int out_size)
{
    const float* x        = (const float*)d_in[0];
    const float* pos      = (const float*)d_in[1];
    const float* c        = (const float*)d_in[2];
    const float* Wq = (const float*)d_in[3];  const float* bq = (const float*)d_in[4];
    const float* Wk = (const float*)d_in[5];  const float* bk = (const float*)d_in[6];
    const float* Wv = (const float*)d_in[7];  const float* bv = (const float*)d_in[8];
    const float* Wo = (const float*)d_in[9];  const float* bo = (const float*)d_in[10];
    const float* W1 = (const float*)d_in[11]; const float* b1 = (const float*)d_in[12];
    const float* W2 = (const float*)d_in[13]; const float* b2 = (const float*)d_in[14];
    const float* ln1s = (const float*)d_in[15]; const float* ln1b = (const float*)d_in[16];
    const float* ln2s = (const float*)d_in[17]; const float* ln2b = (const float*)d_in[18];
    const float* log_tau    = (const float*)d_in[19];
    const float* attn_scale = (const float*)d_in[20];
    float* out = (float*)d_out;

    float *p_xnorm, *p_qkv, *p_attn, *p_x1, *p_x2n, *p_h1;
    float *p_wqkvt, *p_bqkv, *p_wot, *p_w1t, *p_w2t;
    cudaGetSymbolAddress((void**)&p_xnorm, g_xnorm);
    cudaGetSymbolAddress((void**)&p_qkv, g_qkv);
    cudaGetSymbolAddress((void**)&p_attn, g_attn);
    cudaGetSymbolAddress((void**)&p_x1, g_x1);
    cudaGetSymbolAddress((void**)&p_x2n, g_x2n);
    cudaGetSymbolAddress((void**)&p_h1, g_h1);
    cudaGetSymbolAddress((void**)&p_wqkvt, g_wqkvt);
    cudaGetSymbolAddress((void**)&p_bqkv, g_bqkv);
    cudaGetSymbolAddress((void**)&p_wot, g_wot);
    cudaGetSymbolAddress((void**)&p_w1t, g_w1t);
    cudaGetSymbolAddress((void**)&p_w2t, g_w2t);

    cudaFuncSetAttribute(mma_gemm<1>, cudaFuncAttributeMaxDynamicSharedMemorySize, GEMM_SMEM_BYTES);
    cudaFuncSetAttribute(mma_gemm<2>, cudaFuncAttributeMaxDynamicSharedMemorySize, GEMM_SMEM_BYTES);
    cudaFuncSetAttribute(mma_gemm<3>, cudaFuncAttributeMaxDynamicSharedMemorySize, GEMM_SMEM_BYTES);

    const int M = BB * NN;   // 4096

    // batched weight transposes ([K,N] -> [N,K], tf32-rounded)
    TJobs jobs;
    jobs.in[0] = Wq; jobs.out[0] = p_wqkvt;                jobs.R[0] = DIM; jobs.C[0] = DIM;
    jobs.in[1] = Wk; jobs.out[1] = p_wqkvt + DIM * DIM;    jobs.R[1] = DIM; jobs.C[1] = DIM;
    jobs.in[2] = Wv; jobs.out[2] = p_wqkvt + 2 * DIM * DIM; jobs.R[2] = DIM; jobs.C[2] = DIM;
    jobs.in[3] = Wo; jobs.out[3] = p_wot;                  jobs.R[3] = DIM; jobs.C[3] = DIM;
    jobs.in[4] = W1; jobs.out[4] = p_w1t;                  jobs.R[4] = DIM; jobs.C[4] = FF;
    jobs.in[5] = W2; jobs.out[5] = p_w2t;                  jobs.R[5] = FF;  jobs.C[5] = DIM;
    transpose_batch<<<dim3(FF / 32, FF / 32, 6), dim3(32, 8)>>>(jobs);
    concat_bias<<<(3 * DIM + 255) / 256, 256>>>(bq, bk, bv);

    // 1. LN1
    ln_kernel<<<M, 256>>>(x, ln1s, ln1b, p_xnorm);

    // 2. fused QKV projection (heads layout epilogue, demux by column)
    mma_gemm<1><<<dim3(3 * DIM / 128, M / 128), 256, GEMM_SMEM_BYTES>>>(
        p_xnorm, p_wqkvt, p_bqkv, nullptr, p_qkv, M, 3 * DIM, DIM);

    // 3. distances + top-k
    pnsq_kernel<<<(BB * NN + 255) / 256, 256>>>(pos);
    dist_kernel<<<dim3(NN / 32, NN / 32, BB), dim3(32, 8)>>>(pos, c);
    topk_kernel<<<BB * NN, 256>>>();

    // 4. attention
    attn_kernel<<<BB * NH * NN / 8, 256>>>(log_tau, attn_scale);

    // 5. output projection + residual
    dim3 g512(DIM / 128, M / 128);
    mma_gemm<2><<<g512, 256, GEMM_SMEM_BYTES>>>(p_attn, p_wot, bo, x, p_x1, M, DIM, DIM);

    // 6. LN2
    ln_kernel<<<M, 256>>>(p_x1, ln2s, ln2b, p_x2n);

    // 7. FFN
    dim3 gff1(FF / 128, M / 128);
    mma_gemm<3><<<gff1, 256, GEMM_SMEM_BYTES>>>(p_x2n, p_w1t, b1, nullptr, p_h1, M, FF, DIM);
    mma_gemm<2><<<g512, 256, GEMM_SMEM_BYTES>>>(p_h1, p_w2t, b2, p_x1, out, M, DIM, FF);
}

// round 14
// speedup vs baseline: 1.0047x; 1.0047x over previous
#include <cuda_runtime.h>
#include <math.h>
#include <stdint.h>

#define BB   2
#define NN   2048
#define DIM  512
#define NH   8
#define KNBR 32
#define PD   16
#define HD   64
#define FF   2048

// ======================= helpers =============================================
__device__ __forceinline__ uint32_t smem_u32(const void* p) {
    uint32_t a;
    asm("{ .reg .u64 t; cvta.to.shared.u64 t, %1; cvt.u32.u64 %0, t; }"
        : "=r"(a) : "l"(p));
    return a;
}

__device__ __forceinline__ float rtf32(float x) {
    uint32_t u;
    asm("cvt.rna.tf32.f32 %0, %1;" : "=r"(u) : "f"(x));
    return __uint_as_float(u);
}

// ======================= scratch =============================================
__device__ float g_xnorm[BB*NN*DIM];
__device__ float g_qkv[3*BB*NN*DIM];          // q | k | v (heads layout each)
__device__ int   g_tidx[BB*NN*KNBR];
__device__ float g_tdist[BB*NN*KNBR];
__device__ float g_attn[BB*NN*DIM];
__device__ float g_x1[BB*NN*DIM];
__device__ float g_x2n[BB*NN*DIM];
__device__ float g_h1[(size_t)BB*NN*FF];
__device__ float g_pninv[BB*NN];              // 1/(1 - c*|pos|^2)
// transposed (N,K) tf32-rounded weights
__device__ float g_wqkvt[3*DIM*DIM];          // fused QKV [1536, 512]
__device__ float g_bqkv[3*DIM];
__device__ float g_wot[DIM*DIM];
__device__ float g_w1t[FF*DIM];
__device__ float g_w2t[DIM*FF];

// ======================= batched weight transpose (+tf32 round) ==============
struct TJobs {
    const float* in[6];
    float* out[6];
    int R[6], C[6];
};

__global__ __launch_bounds__(256) void transpose_batch(TJobs jobs)
{
    int z = blockIdx.z;
    int R = jobs.R[z], C = jobs.C[z];
    int c0 = blockIdx.x * 32, r0 = blockIdx.y * 32;
    if (c0 >= C || r0 >= R) return;
    const float* in = jobs.in[z];
    float* out = jobs.out[z];
    __shared__ float t[32][33];
    int x = threadIdx.x, y = threadIdx.y;
#pragma unroll
    for (int dy = 0; dy < 32; dy += 8)
        t[y + dy][x] = in[(size_t)(r0 + y + dy) * C + c0 + x];
    __syncthreads();
#pragma unroll
    for (int dy = 0; dy < 32; dy += 8)
        out[(size_t)(c0 + y + dy) * R + r0 + x] = rtf32(t[x][y + dy]);
}

__global__ void concat_bias(const float* __restrict__ bq,
                            const float* __restrict__ bk,
                            const float* __restrict__ bv)
{
    int i = blockIdx.x * blockDim.x + threadIdx.x;
    if (i < 3 * DIM) {
        float v = (i < DIM) ? bq[i] : (i < 2 * DIM ? bk[i - DIM] : bv[i - 2 * DIM]);
        g_bqkv[i] = v;
    }
}

// ======================= mma.sync tf32 GEMM ==================================
#define SA 36                        // padded row stride (floats)
#define STAGE_FLOATS (2 * 128 * SA)  // A tile + B tile = 9216 floats
#define SMEM_FLOATS  (2 * STAGE_FLOATS)
#define GEMM_SMEM_BYTES (SMEM_FLOATS * 4)   // 73728

__device__ __forceinline__ void issue_tile(
    const float* __restrict__ A, const float* __restrict__ Bt,
    float* sm, int row0, int col0, int Kd, int t, int tid)
{
    float* as = sm + (t & 1) * STAGE_FLOATS;
    float* bs = as + 128 * SA;
    int k0 = t * 32;
#pragma unroll
    for (int it = 0; it < 4; it++) {
        int cch = tid + it * 256;            // 0..1023
        int r = cch >> 3, k4 = (cch & 7) * 4;
        uint32_t da = smem_u32(as + r * SA + k4);
        const float* ga = A + (size_t)(row0 + r) * Kd + k0 + k4;
        asm volatile("cp.async.cg.shared.global [%0], [%1], 16;" :: "r"(da), "l"(ga));
        uint32_t db = smem_u32(bs + r * SA + k4);
        const float* gb = Bt + (size_t)(col0 + r) * Kd + k0 + k4;
        asm volatile("cp.async.cg.shared.global [%0], [%1], 16;" :: "r"(db), "l"(gb));
    }
    asm volatile("cp.async.commit_group;" ::: "memory");
}

template<int EPI>
__global__ __launch_bounds__(256, 2) void mma_gemm(
    const float* __restrict__ A, const float* __restrict__ Bt,
    const float* __restrict__ bias, const float* __restrict__ resid,
    float* __restrict__ C, int M, int Nd, int Kd)
{
    extern __shared__ __align__(16) float sm[];
    int tid = threadIdx.x, wid = tid >> 5, lane = tid & 31;
    int g = lane >> 2, tig = lane & 3;
    int row0 = blockIdx.y * 128, col0 = blockIdx.x * 128;
    int m0 = (wid & 3) * 32, n0 = (wid >> 2) * 64;

    float acc[2][8][4];
#pragma unroll
    for (int mt = 0; mt < 2; mt++)
#pragma unroll
        for (int nt = 0; nt < 8; nt++)
#pragma unroll
            for (int u = 0; u < 4; u++) acc[mt][nt][u] = 0.f;

    const int tiles = Kd >> 5;
    issue_tile(A, Bt, sm, row0, col0, Kd, 0, tid);

    for (int t = 0; t < tiles; t++) {
        if (t + 1 < tiles) {
            issue_tile(A, Bt, sm, row0, col0, Kd, t + 1, tid);
            asm volatile("cp.async.wait_group 1;" ::: "memory");
        } else {
            asm volatile("cp.async.wait_group 0;" ::: "memory");
        }
        __syncthreads();

        const float* as = sm + (t & 1) * STAGE_FLOATS;
        const float* bs = as + 128 * SA;
#pragma unroll
        for (int kk = 0; kk < 32; kk += 8) {
            uint32_t a[2][4];
#pragma unroll
            for (int mt = 0; mt < 2; mt++) {
                const float* ar0 = as + (m0 + mt * 16 + g) * SA + kk;
                const float* ar1 = as + (m0 + mt * 16 + g + 8) * SA + kk;
                a[mt][0] = __float_as_uint(ar0[tig]);
                a[mt][1] = __float_as_uint(ar1[tig]);
                a[mt][2] = __float_as_uint(ar0[tig + 4]);
                a[mt][3] = __float_as_uint(ar1[tig + 4]);
            }
            uint32_t b[8][2];
#pragma unroll
            for (int nt = 0; nt < 8; nt++) {
                const float* br = bs + (n0 + nt * 8 + g) * SA + kk;
                b[nt][0] = __float_as_uint(br[tig]);
                b[nt][1] = __float_as_uint(br[tig + 4]);
            }
#pragma unroll
            for (int mt = 0; mt < 2; mt++)
#pragma unroll
                for (int nt = 0; nt < 8; nt++)
                    asm volatile(
                        "mma.sync.aligned.m16n8k8.row.col.f32.tf32.tf32.f32 "
                        "{%0,%1,%2,%3}, {%4,%5,%6,%7}, {%8,%9}, {%0,%1,%2,%3};"
                        : "+f"(acc[mt][nt][0]), "+f"(acc[mt][nt][1]),
                          "+f"(acc[mt][nt][2]), "+f"(acc[mt][nt][3])
                        : "r"(a[mt][0]), "r"(a[mt][1]), "r"(a[mt][2]), "r"(a[mt][3]),
                          "r"(b[nt][0]), "r"(b[nt][1]));
        }
        __syncthreads();
    }

    // ---- epilogue straight from registers ----
#pragma unroll
    for (int mt = 0; mt < 2; mt++) {
        int ra = row0 + m0 + mt * 16 + g;      // rows ra and ra+8
#pragma unroll
        for (int nt = 0; nt < 8; nt++) {
            int cc = col0 + n0 + nt * 8 + tig * 2;
            float b0 = bias[cc], b1 = bias[cc + 1];
            float v0 = acc[mt][nt][0] + b0, v1 = acc[mt][nt][1] + b1;
            float v2 = acc[mt][nt][2] + b0, v3 = acc[mt][nt][3] + b1;

            if (EPI == 1) {
                int which = cc >> 9;
                int rem = cc & 511;
                int h = rem >> 6, d0 = rem & 63;
                float* base = C + (size_t)which * (BB * NN * DIM);
                int bb0 = ra >> 11, n_0 = ra & (NN - 1);
                int bb1 = (ra + 8) >> 11, n_1 = (ra + 8) & (NN - 1);
                float* d0p = base + (((size_t)bb0 * NH + h) * NN + n_0) * HD + d0;
                float* d1p = base + (((size_t)bb1 * NH + h) * NN + n_1) * HD + d0;
                *(float2*)d0p = make_float2(v0, v1);
                *(float2*)d1p = make_float2(v2, v3);
            } else if (EPI == 2) {
                float* p0 = C + (size_t)ra * Nd + cc;
                float* p1 = C + (size_t)(ra + 8) * Nd + cc;
                float2 rv0 = *(const float2*)(resid + (size_t)ra * Nd + cc);
                float2 rv1 = *(const float2*)(resid + (size_t)(ra + 8) * Nd + cc);
                *(float2*)p0 = make_float2(v0 + rv0.x, v1 + rv0.y);
                *(float2*)p1 = make_float2(v2 + rv1.x, v3 + rv1.y);
            } else { // gelu -> tf32
                float vv[4] = {v0, v1, v2, v3};
#pragma unroll
                for (int u = 0; u < 4; u++) {
                    float xg = vv[u];
                    float tt = 0.7978845608028654f * (xg + 0.044715f * xg * xg * xg);
                    vv[u] = rtf32(0.5f * xg * (1.f + tanhf(tt)));
                }
                float* p0 = C + (size_t)ra * Nd + cc;
                float* p1 = C + (size_t)(ra + 8) * Nd + cc;
                *(float2*)p0 = make_float2(vv[0], vv[1]);
                *(float2*)p1 = make_float2(vv[2], vv[3]);
            }
        }
    }
}

// ======================= LayerNorm (tf32-rounded output) =====================
__global__ __launch_bounds__(256) void ln_kernel(
    const float* __restrict__ x, const float* __restrict__ scale,
    const float* __restrict__ bias, float* __restrict__ out)
{
    int row = blockIdx.x;
    int tid = threadIdx.x;
    const float* xr = x + (size_t)row * DIM;
    float2 v = ((const float2*)xr)[tid];
    float s  = v.x + v.y;
    float ss = v.x*v.x + v.y*v.y;
    for (int o = 16; o; o >>= 1) {
        s  += __shfl_xor_sync(0xffffffffu, s,  o);
        ss += __shfl_xor_sync(0xffffffffu, ss, o);
    }
    __shared__ float sh_s[8], sh_ss[8];
    int warp = tid >> 5, lane = tid & 31;
    if (lane == 0) { sh_s[warp] = s; sh_ss[warp] = ss; }
    __syncthreads();
    float stot = 0.f, sstot = 0.f;
#pragma unroll
    for (int w = 0; w < 8; w++) { stot += sh_s[w]; sstot += sh_ss[w]; }
    float mean = stot * (1.0f / DIM);
    float var  = sstot * (1.0f / DIM) - mean * mean;
    float inv  = rsqrtf(var + 1e-6f);
    float2 sc = ((const float2*)scale)[tid];
    float2 bi = ((const float2*)bias)[tid];
    float2 o2;
    o2.x = rtf32((v.x - mean) * inv * sc.x + bi.x);
    o2.y = rtf32((v.y - mean) * inv * sc.y + bi.y);
    ((float2*)(out + (size_t)row * DIM))[tid] = o2;
}

// ======================= per-node reciprocal ==================================
__global__ void pninv_kernel(const float* __restrict__ pos, const float* __restrict__ cptr)
{
    int r = blockIdx.x * blockDim.x + threadIdx.x;
    if (r < BB * NN) {
        float s = 0.f;
#pragma unroll
        for (int p = 0; p < PD; p++) { float v = pos[(size_t)r * PD + p]; s += v * v; }
        g_pninv[r] = 1.f / (1.f - cptr[0] * s);
    }
}

// ======================= fused distance + top-K ===============================
// One block per query row (b,i). Select top-32 by monotonic surrogate
// arg = 1 + 2c*ds*inv_i*inv_j (acoshf deferred to the 32 winners).
__global__ __launch_bounds__(256) void dist_topk(
    const float* __restrict__ pos, const float* __restrict__ cptr)
{
    const float INF = __int_as_float(0x7f800000);
    int row = blockIdx.x;              // b*NN + i
    int b = row >> 11, i = row & (NN - 1);
    int tid = threadIdx.x, wid = tid >> 5, lane = tid & 31;

    __shared__ float args[NN];
    __shared__ float cv[8][32];
    __shared__ int   ci[8][32];
    __shared__ float winv[32];
    __shared__ int   wini[32];
    __shared__ float pish[16];

    float c = cptr[0];
    const float* posb = pos + (size_t)b * NN * PD;
    if (tid < 16) pish[tid] = posb[(size_t)i * PD + tid];
    __syncthreads();

    float pi0[PD];
#pragma unroll
    for (int p = 0; p < PD; p++) pi0[p] = pish[p];
    float inv_i = g_pninv[row];
    float coef = 2.f * c * inv_i;

    // ---- phase A: compute args for all j (coalesced float4 loads, L1/L2-hot)
#pragma unroll
    for (int rr = 0; rr < 8; rr++) {
        int j = rr * 256 + tid;
        const float4* pj = (const float4*)(posb + (size_t)j * PD);
        float4 a0 = pj[0], a1 = pj[1], a2 = pj[2], a3 = pj[3];
        float d, ds;
        d = pi0[0]  - a0.x; ds = d * d;
        d = pi0[1]  - a0.y; ds = fmaf(d, d, ds);
        d = pi0[2]  - a0.z; ds = fmaf(d, d, ds);
        d = pi0[3]  - a0.w; ds = fmaf(d, d, ds);
        d = pi0[4]  - a1.x; ds = fmaf(d, d, ds);
        d = pi0[5]  - a1.y; ds = fmaf(d, d, ds);
        d = pi0[6]  - a1.z; ds = fmaf(d, d, ds);
        d = pi0[7]  - a1.w; ds = fmaf(d, d, ds);
        d = pi0[8]  - a2.x; ds = fmaf(d, d, ds);
        d = pi0[9]  - a2.y; ds = fmaf(d, d, ds);
        d = pi0[10] - a2.z; ds = fmaf(d, d, ds);
        d = pi0[11] - a2.w; ds = fmaf(d, d, ds);
        d = pi0[12] - a3.x; ds = fmaf(d, d, ds);
        d = pi0[13] - a3.y; ds = fmaf(d, d, ds);
        d = pi0[14] - a3.z; ds = fmaf(d, d, ds);
        d = pi0[15] - a3.w; ds = fmaf(d, d, ds);
        float inv_j = g_pninv[b * NN + j];
        args[j] = fmaf(coef * inv_j, ds, 1.f);
    }
    __syncthreads();

    // ---- phase B: each warp extracts top-32 of its 256-element chunk (shfl only)
    float v[8];
#pragma unroll
    for (int r = 0; r < 8; r++) v[r] = args[wid * 256 + r * 32 + lane];

    for (int it = 0; it < KNBR; it++) {
        float best = v[0]; int br = 0;
#pragma unroll
        for (int r = 1; r < 8; r++) if (v[r] < best) { best = v[r]; br = r; }
        int bidx = wid * 256 + br * 32 + lane;
        float bv = best; int bi = bidx;
#pragma unroll
        for (int o = 16; o; o >>= 1) {
            float ov = __shfl_xor_sync(0xffffffffu, bv, o);
            int   oi = __shfl_xor_sync(0xffffffffu, bi, o);
            if (ov < bv || (ov == bv && oi < bi)) { bv = ov; bi = oi; }
        }
        if (bidx == bi) v[br] = INF;         // winner lane removes its element
        if (lane == 0) { cv[wid][it] = bv; ci[wid][it] = bi; }
    }
    __syncthreads();

    // ---- phase C: warp 0 merges 8x32 candidates -> global top-32
    if (wid == 0) {
        float mv[8]; int mi[8];
#pragma unroll
        for (int r = 0; r < 8; r++) { mv[r] = cv[r][lane]; mi[r] = ci[r][lane]; }

        for (int it = 0; it < KNBR; it++) {
            float best = mv[0]; int bmi = mi[0], br = 0;
#pragma unroll
            for (int r = 1; r < 8; r++)
                if (mv[r] < best || (mv[r] == best && mi[r] < bmi)) {
                    best = mv[r]; bmi = mi[r]; br = r;
                }
            float bv = best; int bi = bmi;
#pragma unroll
            for (int o = 16; o; o >>= 1) {
                float ov = __shfl_xor_sync(0xffffffffu, bv, o);
                int   oi = __shfl_xor_sync(0xffffffffu, bi, o);
                if (ov < bv || (ov == bv && oi < bi)) { bv = ov; bi = oi; }
            }
            if (mi[br] == bi && mv[br] == bv) mv[br] = INF;
            if (lane == 0) { winv[it] = bv; wini[it] = bi; }
        }
        __syncwarp();

        // finalize: 32 lanes -> 32 winners; apply clamp + acoshf now
        float arg = winv[lane];
        int j = wini[lane];
        float dfin = acoshf(fmaxf(arg, 1.f + 1e-7f)) * rsqrtf(c);
        g_tdist[(size_t)row * KNBR + lane] = dfin;
        g_tidx [(size_t)row * KNBR + lane] = j;
    }
}

// ======================= kNN attention (warp per (b,h,i)) ====================
__global__ __launch_bounds__(256) void attn_kernel(
    const float* __restrict__ log_tau, const float* __restrict__ attn_scale)
{
    const float* gq = g_qkv;
    const float* gk = g_qkv + BB * NN * DIM;
    const float* gv = g_qkv + 2 * BB * NN * DIM;

    int warp = threadIdx.x >> 5, lane = threadIdx.x & 31;
    int gw = blockIdx.x * 8 + warp;
    int i  = gw % NN;
    int bh = gw / NN;
    int b  = bh / NH, h = bh % NH;

    __shared__ float qs[8][64];
    __shared__ float ws[8][32];
    __shared__ int   is[8][32];

    const float* qrow = gq + ((size_t)bh * NN + i) * HD;
    qs[warp][lane]      = qrow[lane];
    qs[warp][lane + 32] = qrow[lane + 32];
    __syncwarp();

    int rowk  = b * NN + i;
    int idx   = g_tidx [(size_t)rowk * KNBR + lane];
    float dj  = g_tdist[(size_t)rowk * KNBR + lane];

    const float* krow = gk + ((size_t)bh * NN + idx) * HD;
    float dot = 0.f;
#pragma unroll
    for (int d4 = 0; d4 < HD; d4 += 4) {
        float4 kv = *(const float4*)(krow + d4);
        dot += qs[warp][d4] * kv.x + qs[warp][d4 + 1] * kv.y
             + qs[warp][d4 + 2] * kv.z + qs[warp][d4 + 3] * kv.w;
    }
    float tau = fmaxf(expf(log_tau[0]), 1e-8f);
    float s = attn_scale[0] * tanhf(dot * 0.125f - dj / tau);

    float m = s;
    for (int o = 16; o; o >>= 1) m = fmaxf(m, __shfl_xor_sync(0xffffffffu, m, o));
    float e = expf(s - m);
    float sum = e;
    for (int o = 16; o; o >>= 1) sum += __shfl_xor_sync(0xffffffffu, sum, o);
    float w = e / sum;

    ws[warp][lane] = w; is[warp][lane] = idx;
    __syncwarp();

    float a0 = 0.f, a1 = 0.f;
#pragma unroll
    for (int j = 0; j < KNBR; j++) {
        const float* vrow = gv + ((size_t)bh * NN + is[warp][j]) * HD;
        float wj = ws[warp][j];
        a0 += wj * vrow[lane];
        a1 += wj * vrow[lane + 32];
    }
    float* orow = g_attn + ((size_t)(b * NN + i)) * DIM + h * HD;
    orow[lane]      = rtf32(a0);
    orow[lane + 32] = rtf32(a1);
}

// ======================= launch ==============================================
extern "C" void kernel_launch(void* const* d_in, const int* in_sizes, int n_in,
                              void* d_out, int out_size)
{
    const float* x        = (const float*)d_in[0];
    const float* pos      = (const float*)d_in[1];
    const float* c        = (const float*)d_in[2];
    const float* Wq = (const float*)d_in[3];  const float* bq = (const float*)d_in[4];
    const float* Wk = (const float*)d_in[5];  const float* bk = (const float*)d_in[6];
    const float* Wv = (const float*)d_in[7];  const float* bv = (const float*)d_in[8];
    const float* Wo = (const float*)d_in[9];  const float* bo = (const float*)d_in[10];
    const float* W1 = (const float*)d_in[11]; const float* b1 = (const float*)d_in[12];
    const float* W2 = (const float*)d_in[13]; const float* b2 = (const float*)d_in[14];
    const float* ln1s = (const float*)d_in[15]; const float* ln1b = (const float*)d_in[16];
    const float* ln2s = (const float*)d_in[17]; const float* ln2b = (const float*)d_in[18];
    const float* log_tau    = (const float*)d_in[19];
    const float* attn_scale = (const float*)d_in[20];
    float* out = (float*)d_out;

    float *p_xnorm, *p_qkv, *p_attn, *p_x1, *p_x2n, *p_h1;
    float *p_wqkvt, *p_bqkv, *p_wot, *p_w1t, *p_w2t;
    cudaGetSymbolAddress((void**)&p_xnorm, g_xnorm);
    cudaGetSymbolAddress((void**)&p_qkv, g_qkv);
    cudaGetSymbolAddress((void**)&p_attn, g_attn);
    cudaGetSymbolAddress((void**)&p_x1, g_x1);
    cudaGetSymbolAddress((void**)&p_x2n, g_x2n);
    cudaGetSymbolAddress((void**)&p_h1, g_h1);
    cudaGetSymbolAddress((void**)&p_wqkvt, g_wqkvt);
    cudaGetSymbolAddress((void**)&p_bqkv, g_bqkv);
    cudaGetSymbolAddress((void**)&p_wot, g_wot);
    cudaGetSymbolAddress((void**)&p_w1t, g_w1t);
    cudaGetSymbolAddress((void**)&p_w2t, g_w2t);

    cudaFuncSetAttribute(mma_gemm<1>, cudaFuncAttributeMaxDynamicSharedMemorySize, GEMM_SMEM_BYTES);
    cudaFuncSetAttribute(mma_gemm<2>, cudaFuncAttributeMaxDynamicSharedMemorySize, GEMM_SMEM_BYTES);
    cudaFuncSetAttribute(mma_gemm<3>, cudaFuncAttributeMaxDynamicSharedMemorySize, GEMM_SMEM_BYTES);

    const int M = BB * NN;   // 4096

    // batched weight transposes ([K,N] -> [N,K], tf32-rounded)
    TJobs jobs;
    jobs.in[0] = Wq; jobs.out[0] = p_wqkvt;                 jobs.R[0] = DIM; jobs.C[0] = DIM;
    jobs.in[1] = Wk; jobs.out[1] = p_wqkvt + DIM * DIM;     jobs.R[1] = DIM; jobs.C[1] = DIM;
    jobs.in[2] = Wv; jobs.out[2] = p_wqkvt + 2 * DIM * DIM; jobs.R[2] = DIM; jobs.C[2] = DIM;
    jobs.in[3] = Wo; jobs.out[3] = p_wot;                   jobs.R[3] = DIM; jobs.C[3] = DIM;
    jobs.in[4] = W1; jobs.out[4] = p_w1t;                   jobs.R[4] = DIM; jobs.C[4] = FF;
    jobs.in[5] = W2; jobs.out[5] = p_w2t;                   jobs.R[5] = FF;  jobs.C[5] = DIM;
    transpose_batch<<<dim3(FF / 32, FF / 32, 6), dim3(32, 8)>>>(jobs);
    concat_bias<<<(3 * DIM + 255) / 256, 256>>>(bq, bk, bv);

    // 1. LN1
    ln_kernel<<<M, 256>>>(x, ln1s, ln1b, p_xnorm);

    // 2. fused QKV projection (heads layout epilogue, demux by column)
    mma_gemm<1><<<dim3(3 * DIM / 128, M / 128), 256, GEMM_SMEM_BYTES>>>(
        p_xnorm, p_wqkvt, p_bqkv, nullptr, p_qkv, M, 3 * DIM, DIM);

    // 3. fused distances + top-k (deferred acosh)
    pninv_kernel<<<(BB * NN + 255) / 256, 256>>>(pos, c);
    dist_topk<<<BB * NN, 256>>>(pos, c);

    // 4. attention
    attn_kernel<<<BB * NH * NN / 8, 256>>>(log_tau, attn_scale);

    // 5. output projection + residual
    dim3 g512(DIM / 128, M / 128);
    mma_gemm<2><<<g512, 256, GEMM_SMEM_BYTES>>>(p_attn, p_wot, bo, x, p_x1, M, DIM, DIM);

    // 6. LN2
    ln_kernel<<<M, 256>>>(p_x1, ln2s, ln2b, p_x2n);

    // 7. FFN
    dim3 gff1(FF / 128, M / 128);
    mma_gemm<3><<<gff1, 256, GEMM_SMEM_BYTES>>>(p_x2n, p_w1t, b1, nullptr, p_h1, M, FF, DIM);
    mma_gemm<2><<<g512, 256, GEMM_SMEM_BYTES>>>(p_h1, p_w2t, b2, p_x1, out, M, DIM, FF);
}